// round 15
// baseline (speedup 1.0000x reference)
#include <cuda_runtime.h>
#include <cuda_fp16.h>
#include <mma.h>
#include <cstdint>

using namespace nvcuda;

#define D_MODEL 768
#define HEADS   12
#define D_HEAD  64
#define NB      16
#define SP      256
#define SI      1024
#define TOKP    (NB*SP)     /* 4096  */
#define TOKI    (NB*SI)     /* 16384 */
#define WELEM   (D_MODEL*D_MODEL)

// ---------------- scratch (device globals: no allocations allowed) ----------------
__device__ float  g_prompt0[TOKP*D_MODEL];
__device__ float  g_p1     [TOKP*D_MODEL];
__device__ float  g_p2     [TOKP*D_MODEL];
__device__ __half g_x   [TOKP*D_MODEL];
__device__ __half g_xi  [TOKI*D_MODEL];
__device__ __half g_q   [TOKP*D_MODEL];
__device__ __half g_k   [TOKI*D_MODEL];
__device__ __half g_v   [TOKI*D_MODEL];
__device__ __half g_attn[TOKP*D_MODEL];
__device__ __half g_h   [TOKP*D_MODEL];
__device__ __half g_wh  [10][WELEM];   /* fp16 weights, [k][n] layout */

// ---------------- helpers ----------------
__device__ __forceinline__ void cpa16(uint32_t sa, const void* g) {
    asm volatile("cp.async.cg.shared.global [%0], [%1], 16;" :: "r"(sa), "l"(g));
}
__device__ __forceinline__ void cp_commit() { asm volatile("cp.async.commit_group;"); }
__device__ __forceinline__ uint32_t su32(const void* p) {
    return (uint32_t)__cvta_generic_to_shared(p);
}

// ---------------- fused weight fp32 -> fp16 (all 10 matrices, one launch) ----------------
struct WSrc { const float* p[10]; };
__global__ void half_w_all_kernel(WSrc S, __half* __restrict__ dst) {
    int mat = blockIdx.y;
    int i = blockIdx.x * blockDim.x + threadIdx.x;
    const float4* s = (const float4*)S.p[mat];
    float4 v = s[i];
    __half* d = dst + (size_t)mat * WELEM + (size_t)i * 4;
    *(__half2*)&d[0] = __floats2half2_rn(v.x, v.y);
    *(__half2*)&d[2] = __floats2half2_rn(v.z, v.w);
}

// ---------------- elementwise add (float4) ----------------
__global__ void add4_kernel(const float4* __restrict__ a, const float4* __restrict__ b,
                            float4* __restrict__ o, int n4) {
    int i = blockIdx.x * blockDim.x + threadIdx.x;
    if (i < n4) {
        float4 x = a[i], y = b[i];
        x.x += y.x; x.y += y.y; x.z += y.z; x.w += y.w;
        o[i] = x;
    }
}

// ---------------- (optional add) + layernorm -> fp16 ----------------
__global__ void addln_kernel(const float* __restrict__ a, const float* __restrict__ b,
                             const float* __restrict__ g, const float* __restrict__ be,
                             __half* __restrict__ o) {
    int row = blockIdx.x;
    const float* pa = a + (size_t)row * D_MODEL;
    const float* pb = b ? b + (size_t)row * D_MODEL : nullptr;
    float x[3];
    float s = 0.f, sq = 0.f;
#pragma unroll
    for (int j = 0; j < 3; j++) {
        int i = threadIdx.x + j * 256;
        float v = pa[i];
        if (pb) v += pb[i];
        x[j] = v; s += v; sq += v * v;
    }
    __shared__ float sb[16];
    unsigned wid = threadIdx.x >> 5, lane = threadIdx.x & 31;
#pragma unroll
    for (int off = 16; off; off >>= 1) {
        s  += __shfl_xor_sync(0xffffffffu, s,  off);
        sq += __shfl_xor_sync(0xffffffffu, sq, off);
    }
    if (lane == 0) { sb[wid] = s; sb[8 + wid] = sq; }
    __syncthreads();
    if (threadIdx.x < 32) {
        float s2 = (lane < 8) ? sb[lane] : 0.f;
        float q2 = (lane < 8) ? sb[8 + lane] : 0.f;
#pragma unroll
        for (int off = 4; off; off >>= 1) {
            s2 += __shfl_xor_sync(0xffffffffu, s2, off);
            q2 += __shfl_xor_sync(0xffffffffu, q2, off);
        }
        if (lane == 0) { sb[0] = s2; sb[1] = q2; }
    }
    __syncthreads();
    float mean = sb[0] * (1.f / 768.f);
    float var  = sb[1] * (1.f / 768.f) - mean * mean;
    float rs   = rsqrtf(var + 1e-5f);
#pragma unroll
    for (int j = 0; j < 3; j++) {
        int i = threadIdx.x + j * 256;
        o[(size_t)row * D_MODEL + i] = __float2half_rn((x[j] - mean) * rs * g[i] + be[i]);
    }
}

// ---------------- wmma fp16 typedefs ----------------
using HFragA  = wmma::fragment<wmma::matrix_a, 16, 16, 16, __half, wmma::row_major>;
using HFragB  = wmma::fragment<wmma::matrix_b, 16, 16, 16, __half, wmma::row_major>;
using HFragBT = wmma::fragment<wmma::matrix_b, 16, 16, 16, __half, wmma::col_major>;
using HFragC  = wmma::fragment<wmma::accumulator, 16, 16, 16, float>;

extern __shared__ __align__(16) char smraw[];

// ===== dense GEMM: 128x128xK64 fp16, warp 64x32, cp.async 3-stage, 1 sync/iter =====
// per-z: A pointer, y-limit (blocks), weights, bias, resid, outputs, flags
struct DZ {
    const __half* Ap[3];
    const __half* W[3];
    const float*  Bi[3];
    const float*  R[3];
    float*  Cf[3];
    __half* Ch[3];
    int fl[3];
    int ylim[3];
};

#define D_ALD 72
#define D_BLD 136
#define D_ASZ (128 * D_ALD)
#define D_BSZ (64 * D_BLD)
#define D_STG (D_ASZ + D_BSZ)        /* 17920 halves = 35840 B */
#define D_CLD 132
#define DENSE_SMEM (3 * D_STG * 2)   /* 107520 B; 2 CTAs = 215KB fits */

__global__ __launch_bounds__(256, 2) void dense_gemm_kernel(DZ P) {
    constexpr int K = D_MODEL, N = D_MODEL;
    if (blockIdx.y >= (unsigned)P.ylim[blockIdx.z]) return;
    const __half* A    = P.Ap[blockIdx.z];
    const __half* W    = P.W[blockIdx.z];
    const float* bias  = P.Bi[blockIdx.z];
    const float* resid = P.R[blockIdx.z];
    float*  Cf         = P.Cf[blockIdx.z];
    __half* Ch         = P.Ch[blockIdx.z];
    int flags          = P.fl[blockIdx.z];

    __half* sm = (__half*)smraw;
    int tid = threadIdx.x;
    int m0 = blockIdx.y * 128, n0 = blockIdx.x * 128;
    int warp = tid >> 5, wm = warp & 1, wn = warp >> 1;

    HFragC acc[4][2];
#pragma unroll
    for (int i = 0; i < 4; i++)
#pragma unroll
        for (int j = 0; j < 2; j++) wmma::fill_fragment(acc[i][j], 0.f);

    auto load_tile = [&](int s, int k0) {
        __half* As = sm + s * D_STG;
        __half* Bs = As + D_ASZ;
#pragma unroll
        for (int i = 0; i < 4; i++) {
            int p = tid + i * 256, r = p >> 3, c = (p & 7) * 8;
            cpa16(su32(&As[r * D_ALD + c]), &A[(size_t)(m0 + r) * K + k0 + c]);
        }
#pragma unroll
        for (int i = 0; i < 4; i++) {
            int p = tid + i * 256, r = p >> 4, c = (p & 15) * 8;
            cpa16(su32(&Bs[r * D_BLD + c]), &W[(size_t)(k0 + r) * N + n0 + c]);
        }
        cp_commit();
    };

    const int nk = K / 64;   // 12
    load_tile(0, 0);
    load_tile(1, 64);
    for (int kt = 0; kt < nk; kt++) {
        int s = kt % 3;
        if (kt + 1 < nk) asm volatile("cp.async.wait_group 1;");
        else             asm volatile("cp.async.wait_group 0;");
        __syncthreads();
        if (kt + 2 < nk) load_tile((kt + 2) % 3, (kt + 2) * 64);
        __half* As = sm + s * D_STG;
        __half* Bs = As + D_ASZ;
#pragma unroll
        for (int kk = 0; kk < 64; kk += 16) {
            HFragA fa[4]; HFragB fb[2];
#pragma unroll
            for (int i = 0; i < 4; i++)
                wmma::load_matrix_sync(fa[i], &As[(wm * 64 + i * 16) * D_ALD + kk], D_ALD);
#pragma unroll
            for (int j = 0; j < 2; j++)
                wmma::load_matrix_sync(fb[j], &Bs[kk * D_BLD + wn * 32 + j * 16], D_BLD);
#pragma unroll
            for (int i = 0; i < 4; i++)
#pragma unroll
                for (int j = 0; j < 2; j++) wmma::mma_sync(acc[i][j], fa[i], fb[j], acc[i][j]);
        }
    }
    __syncthreads();
    float* Cs = (float*)smraw;
#pragma unroll
    for (int i = 0; i < 4; i++)
#pragma unroll
        for (int j = 0; j < 2; j++)
            wmma::store_matrix_sync(&Cs[(wm * 64 + i * 16) * D_CLD + wn * 32 + j * 16],
                                    acc[i][j], D_CLD, wmma::mem_row_major);
    __syncthreads();
#pragma unroll
    for (int i = 0; i < 16; i++) {
        int p = tid + i * 256, r = p >> 5, c = (p & 31) * 4;
        float4 v = *(float4*)&Cs[r * D_CLD + c];
        int gc = n0 + c;
        float4 bv = *(const float4*)&bias[gc];
        v.x += bv.x; v.y += bv.y; v.z += bv.z; v.w += bv.w;
        size_t off = (size_t)(m0 + r) * N + gc;
        if (resid) {
            float4 rv = *(const float4*)&resid[off];
            v.x += rv.x; v.y += rv.y; v.z += rv.z; v.w += rv.w;
        }
        if (flags & 1) {
            v.x = fmaxf(v.x, 0.f); v.y = fmaxf(v.y, 0.f);
            v.z = fmaxf(v.z, 0.f); v.w = fmaxf(v.w, 0.f);
        }
        if (flags & 2) {
            *(__half2*)&Ch[off]     = __floats2half2_rn(v.x, v.y);
            *(__half2*)&Ch[off + 2] = __floats2half2_rn(v.z, v.w);
        } else {
            *(float4*)&Cf[off] = v;
        }
    }
}

// ===== fused attention: 128 q-rows x one head per CTA; two-pass softmax, 2 CTAs/SM =====
#define FA_QS 0                      /* 128 x 72 halves = 18432 */
#define FA_KS 18432                  /* 2 x (64 x 72 halves)    = 18432 */
#define FA_VS 36864                  /* 2 x (64 x 72 halves)    = 18432 */
#define FA_SS 55296                  /* 128 x 68 fp32           = 34816 */
#define FA_PS 90112                  /* 128 x 72 halves         = 18432 */
#define FA_MS 108544                 /* 128 fp32 = 512 */
#define FA_LS 109056                 /* 128 fp32 = 512 */
#define FA_SMEM 109568               /* x2 CTAs = 219KB fits */

__global__ __launch_bounds__(256, 2) void fattn_kernel(
    const __half* __restrict__ Q, const __half* __restrict__ Kg,
    const __half* __restrict__ Vg, __half* __restrict__ O, int kv_tokens) {
    const float alpha = 0.125f;
    int z = blockIdx.y, bi = z / HEADS, hi = z % HEADS;
    int m0 = blockIdx.x * 128;
    const __half* Qb = Q  + ((size_t)bi * SP + m0) * D_MODEL + hi * D_HEAD;
    const __half* Kb = Kg + (size_t)bi * kv_tokens * D_MODEL + hi * D_HEAD;
    const __half* Vb = Vg + (size_t)bi * kv_tokens * D_MODEL + hi * D_HEAD;
    __half* Ob = O + ((size_t)bi * SP + m0) * D_MODEL + hi * D_HEAD;

    __half* Qs = (__half*)(smraw + FA_QS);
    __half* Ks = (__half*)(smraw + FA_KS);
    __half* Vs = (__half*)(smraw + FA_VS);
    float*  Ss = (float*)(smraw + FA_SS);
    __half* Ps = (__half*)(smraw + FA_PS);
    float*  Ms = (float*)(smraw + FA_MS);
    float*  Ls = (float*)(smraw + FA_LS);

    int tid = threadIdx.x;
    int warp = tid >> 5, wm = warp & 3, wn = warp >> 2;

#pragma unroll
    for (int i = 0; i < 4; i++) {
        int p = tid + i * 256, r = p >> 3, c = (p & 7) * 8;
        cpa16(su32(&Qs[r * 72 + c]), &Qb[(size_t)r * D_MODEL + c]);
    }
    cp_commit();
    if (tid < 128) { Ms[tid] = -1e30f; Ls[tid] = 0.f; }
    asm volatile("cp.async.wait_group 0;");
    __syncthreads();

    const int nt = kv_tokens / 64;

    auto load_k = [&](int t, int s) {
#pragma unroll
        for (int i = 0; i < 2; i++) {
            int p = tid + i * 256, r = p >> 3, c = (p & 7) * 8;
            cpa16(su32(&Ks[s * 4608 + r * 72 + c]), &Kb[(size_t)(t * 64 + r) * D_MODEL + c]);
        }
    };
    auto load_v = [&](int t, int s) {
#pragma unroll
        for (int i = 0; i < 2; i++) {
            int p = tid + i * 256, r = p >> 3, c = (p & 7) * 8;
            cpa16(su32(&Vs[s * 4608 + r * 72 + c]), &Vb[(size_t)(t * 64 + r) * D_MODEL + c]);
        }
    };
    auto s_mma_store = [&](int s) {
        HFragC sacc[2][2];
#pragma unroll
        for (int i = 0; i < 2; i++)
#pragma unroll
            for (int j = 0; j < 2; j++) wmma::fill_fragment(sacc[i][j], 0.f);
#pragma unroll
        for (int kk = 0; kk < 64; kk += 16) {
            HFragA fa[2]; HFragBT fb[2];
#pragma unroll
            for (int i = 0; i < 2; i++)
                wmma::load_matrix_sync(fa[i], &Qs[(wm * 32 + i * 16) * 72 + kk], 72);
#pragma unroll
            for (int j = 0; j < 2; j++)
                wmma::load_matrix_sync(fb[j], &Ks[s * 4608 + (wn * 32 + j * 16) * 72 + kk], 72);
#pragma unroll
            for (int i = 0; i < 2; i++)
#pragma unroll
                for (int j = 0; j < 2; j++) wmma::mma_sync(sacc[i][j], fa[i], fb[j], sacc[i][j]);
        }
#pragma unroll
        for (int i = 0; i < 2; i++)
#pragma unroll
            for (int j = 0; j < 2; j++)
                wmma::store_matrix_sync(&Ss[(wm * 32 + i * 16) * 68 + wn * 32 + j * 16],
                                        sacc[i][j], 68, wmma::mem_row_major);
    };

    // ---------- PASS 1: row stats (2 threads/row, shfl-combined, fast exp) ----------
    load_k(0, 0); cp_commit();
    for (int t = 0; t < nt; t++) {
        int s = t & 1;
        asm volatile("cp.async.wait_group 0;");
        __syncthreads();
        s_mma_store(s);
        if (t + 1 < nt) { load_k(t + 1, s ^ 1); cp_commit(); }
        __syncthreads();
        {
            int r = tid >> 1, hf = tid & 1;
            const float* Sr = Ss + r * 68 + hf * 32;
            float m_old = Ms[r], l_old = Ls[r];
            float tm = -1e30f;
#pragma unroll
            for (int j = 0; j < 32; j++) tm = fmaxf(tm, Sr[j]);
            tm *= alpha;
            float tmo = __shfl_xor_sync(0xffffffffu, tm, 1);
            float m_new = fmaxf(fmaxf(tm, tmo), m_old);
            float sum = 0.f;
#pragma unroll
            for (int j = 0; j < 32; j++) sum += __expf(Sr[j] * alpha - m_new);
            sum += __shfl_xor_sync(0xffffffffu, sum, 1);
            if (hf == 0) {
                Ls[r] = l_old * __expf(m_old - m_new) + sum;
                Ms[r] = m_new;
            }
        }
        __syncthreads();
    }
    if (tid < 128) Ls[tid] = 1.f / Ls[tid];
    __syncthreads();

    // ---------- PASS 2: P = exp(s-m)/l ; O += P@V ----------
    HFragC oacc[2][2];
#pragma unroll
    for (int i = 0; i < 2; i++)
#pragma unroll
        for (int j = 0; j < 2; j++) wmma::fill_fragment(oacc[i][j], 0.f);

    load_k(0, 0); load_v(0, 0); cp_commit();
    for (int t = 0; t < nt; t++) {
        int s = t & 1;
        asm volatile("cp.async.wait_group 0;");
        __syncthreads();
        s_mma_store(s);
        if (t + 1 < nt) { load_k(t + 1, s ^ 1); load_v(t + 1, s ^ 1); cp_commit(); }
        __syncthreads();
        {
            int r = tid >> 1, cb = (tid & 1) * 32;
            float m = Ms[r], li = Ls[r];
            const float* Sr = Ss + r * 68 + cb;
            __half* Pr = Ps + r * 72 + cb;
#pragma unroll
            for (int j = 0; j < 32; j += 2) {
                float a = __expf(Sr[j] * alpha - m) * li;
                float b = __expf(Sr[j + 1] * alpha - m) * li;
                *(__half2*)&Pr[j] = __floats2half2_rn(a, b);
            }
        }
        __syncthreads();
#pragma unroll
        for (int kk = 0; kk < 64; kk += 16) {
            HFragA fa[2]; HFragB fb[2];
#pragma unroll
            for (int i = 0; i < 2; i++)
                wmma::load_matrix_sync(fa[i], &Ps[(wm * 32 + i * 16) * 72 + kk], 72);
#pragma unroll
            for (int j = 0; j < 2; j++)
                wmma::load_matrix_sync(fb[j], &Vs[s * 4608 + kk * 72 + wn * 32 + j * 16], 72);
#pragma unroll
            for (int i = 0; i < 2; i++)
#pragma unroll
                for (int j = 0; j < 2; j++) wmma::mma_sync(oacc[i][j], fa[i], fb[j], oacc[i][j]);
        }
        __syncthreads();
    }
#pragma unroll
    for (int i = 0; i < 2; i++)
#pragma unroll
        for (int j = 0; j < 2; j++)
            wmma::store_matrix_sync(&Ss[(wm * 32 + i * 16) * 68 + wn * 32 + j * 16],
                                    oacc[i][j], 68, wmma::mem_row_major);
    __syncthreads();
#pragma unroll
    for (int i = 0; i < 16; i++) {
        int p = tid + i * 256;          // 4096 half2 units = 128x64
        int r = p >> 5, c2 = (p & 31) * 2;
        float a = Ss[r * 68 + c2], b = Ss[r * 68 + c2 + 1];
        *(__half2*)&Ob[(size_t)r * D_MODEL + c2] = __floats2half2_rn(a, b);
    }
}

// ---------------- launcher ----------------
extern "C" void kernel_launch(void* const* d_in, const int* in_sizes, int n_in,
                              void* d_out, int out_size) {
    (void)in_sizes; (void)n_in; (void)out_size;
    const float* image  = (const float*)d_in[0];
    const float* prompt = (const float*)d_in[1];
    const float* posi   = (const float*)d_in[2];
    const float* posp   = (const float*)d_in[3];
    const float* ln1g = (const float*)d_in[4],  *ln1b = (const float*)d_in[5];
    const float* ln2g = (const float*)d_in[6],  *ln2b = (const float*)d_in[7];
    const float* ln3g = (const float*)d_in[8],  *ln3b = (const float*)d_in[9];
    const float* lnig = (const float*)d_in[10], *lnib = (const float*)d_in[11];
    const float* pp_wq = (const float*)d_in[12], *pp_bq = (const float*)d_in[13];
    const float* pp_wk = (const float*)d_in[14], *pp_bk = (const float*)d_in[15];
    const float* pp_wv = (const float*)d_in[16], *pp_bv = (const float*)d_in[17];
    const float* pp_wo = (const float*)d_in[18], *pp_bo = (const float*)d_in[19];
    const float* pi_wq = (const float*)d_in[20], *pi_bq = (const float*)d_in[21];
    const float* pi_wk = (const float*)d_in[22], *pi_bk = (const float*)d_in[23];
    const float* pi_wv = (const float*)d_in[24], *pi_bv = (const float*)d_in[25];
    const float* pi_wo = (const float*)d_in[26], *pi_bo = (const float*)d_in[27];
    const float* ff_w1 = (const float*)d_in[28], *ff_b1 = (const float*)d_in[29];
    const float* ff_w2 = (const float*)d_in[30], *ff_b2 = (const float*)d_in[31];
    float* out = (float*)d_out;

    float *prompt0, *p1, *p2;
    __half *x, *xi, *q, *k, *v, *attn, *h, *wh;
    cudaGetSymbolAddress((void**)&prompt0, g_prompt0);
    cudaGetSymbolAddress((void**)&p1,    g_p1);
    cudaGetSymbolAddress((void**)&p2,    g_p2);
    cudaGetSymbolAddress((void**)&x,     g_x);
    cudaGetSymbolAddress((void**)&xi,    g_xi);
    cudaGetSymbolAddress((void**)&q,     g_q);
    cudaGetSymbolAddress((void**)&k,     g_k);
    cudaGetSymbolAddress((void**)&v,     g_v);
    cudaGetSymbolAddress((void**)&attn,  g_attn);
    cudaGetSymbolAddress((void**)&h,     g_h);
    cudaGetSymbolAddress((void**)&wh,    g_wh);

    __half* W[10];
    const float* srcw[10] = {pp_wq, pp_wk, pp_wv, pp_wo, pi_wq, pi_wk, pi_wv, pi_wo, ff_w1, ff_w2};
    for (int i = 0; i < 10; i++) W[i] = wh + (size_t)i * WELEM;

    cudaFuncSetAttribute(dense_gemm_kernel, cudaFuncAttributeMaxDynamicSharedMemorySize, DENSE_SMEM);
    cudaFuncSetAttribute(fattn_kernel,      cudaFuncAttributeMaxDynamicSharedMemorySize, FA_SMEM);

    // 0. all weights -> fp16, one launch
    {
        WSrc S; for (int i = 0; i < 10; i++) S.p[i] = srcw[i];
        half_w_all_kernel<<<dim3(WELEM / 4 / 256, 10), 256>>>(S, wh);
    }
    // 1. prompt0 = prompt + posp
    add4_kernel<<<(TOKP * D_MODEL / 4 + 255) / 256, 256>>>(
        (const float4*)prompt, (const float4*)posp, (float4*)prompt0, TOKP * D_MODEL / 4);
    // 2. x = LN(prompt0) -> fp16
    addln_kernel<<<TOKP, 256>>>(prompt0, nullptr, ln1g, ln1b, x);
    // 3. self QKV fused (z=3) -> fp16
    {
        DZ P = {{x, x, x}, {W[0], W[1], W[2]}, {pp_bq, pp_bk, pp_bv},
                {nullptr, nullptr, nullptr}, {nullptr, nullptr, nullptr},
                {q, k, v}, {2, 2, 2}, {32, 32, 32}};
        dense_gemm_kernel<<<dim3(6, 32, 3), 256, DENSE_SMEM>>>(P);
    }
    // 4. fused self-attention -> attn (fp16)
    fattn_kernel<<<dim3(SP / 128, NB * HEADS), 256, FA_SMEM>>>(q, k, v, attn, SP);
    // 5. p1 = attn @ Wo + bo + prompt (fp32)
    {
        DZ P = {{attn, nullptr, nullptr}, {W[3], nullptr, nullptr}, {pp_bo, nullptr, nullptr},
                {prompt, nullptr, nullptr}, {p1, nullptr, nullptr},
                {nullptr, nullptr, nullptr}, {0, 0, 0}, {32, 0, 0}};
        dense_gemm_kernel<<<dim3(6, 32, 1), 256, DENSE_SMEM>>>(P);
    }
    // 6. x = LN(p1 + prompt0) -> fp16
    addln_kernel<<<TOKP, 256>>>(p1, prompt0, ln2g, ln2b, x);
    // 7. xi = LN(image + posi) -> fp16
    addln_kernel<<<TOKI, 256>>>(image, posi, lnig, lnib, xi);
    // 8+9. cross Q (z=0, 32 y-blocks) + image K,V (z=1,2, 128 y-blocks) in ONE launch
    {
        DZ P = {{x, xi, xi}, {W[4], W[5], W[6]}, {pi_bq, pi_bk, pi_bv},
                {nullptr, nullptr, nullptr}, {nullptr, nullptr, nullptr},
                {q, k, v}, {2, 2, 2}, {32, 128, 128}};
        dense_gemm_kernel<<<dim3(6, 128, 3), 256, DENSE_SMEM>>>(P);
    }
    // 10. fused cross-attention -> attn (fp16)
    fattn_kernel<<<dim3(SP / 128, NB * HEADS), 256, FA_SMEM>>>(q, k, v, attn, SI);
    // 11. p2 = attn @ Wo + bo + p1 (fp32)
    {
        DZ P = {{attn, nullptr, nullptr}, {W[7], nullptr, nullptr}, {pi_bo, nullptr, nullptr},
                {p1, nullptr, nullptr}, {p2, nullptr, nullptr},
                {nullptr, nullptr, nullptr}, {0, 0, 0}, {32, 0, 0}};
        dense_gemm_kernel<<<dim3(6, 32, 1), 256, DENSE_SMEM>>>(P);
    }
    // 12. x = LN(p2 + prompt0) -> fp16
    addln_kernel<<<TOKP, 256>>>(p2, prompt0, ln3g, ln3b, x);
    // 13. h = relu(x @ W1 + b1) -> fp16
    {
        DZ P = {{x, nullptr, nullptr}, {W[8], nullptr, nullptr}, {ff_b1, nullptr, nullptr},
                {nullptr, nullptr, nullptr}, {nullptr, nullptr, nullptr},
                {h, nullptr, nullptr}, {3, 0, 0}, {32, 0, 0}};
        dense_gemm_kernel<<<dim3(6, 32, 1), 256, DENSE_SMEM>>>(P);
    }
    // 14. out = h @ W2 + b2 (fp32 final)
    {
        DZ P = {{h, nullptr, nullptr}, {W[9], nullptr, nullptr}, {ff_b2, nullptr, nullptr},
                {nullptr, nullptr, nullptr}, {out, nullptr, nullptr},
                {nullptr, nullptr, nullptr}, {0, 0, 0}, {32, 0, 0}};
        dense_gemm_kernel<<<dim3(6, 32, 1), 256, DENSE_SMEM>>>(P);
    }
}

// round 16
// speedup vs baseline: 1.4793x; 1.4793x over previous
#include <cuda_runtime.h>
#include <cuda_fp16.h>
#include <mma.h>
#include <cstdint>

using namespace nvcuda;

#define D_MODEL 768
#define HEADS   12
#define D_HEAD  64
#define NB      16
#define SP      256
#define SI      1024
#define TOKP    (NB*SP)     /* 4096  */
#define TOKI    (NB*SI)     /* 16384 */
#define WELEM   (D_MODEL*D_MODEL)

// ---------------- scratch (device globals: no allocations allowed) ----------------
__device__ float  g_prompt0[TOKP*D_MODEL];
__device__ float  g_p1     [TOKP*D_MODEL];
__device__ float  g_p2     [TOKP*D_MODEL];
__device__ __half g_x   [TOKP*D_MODEL];
__device__ __half g_xi  [TOKI*D_MODEL];
__device__ __half g_q   [TOKP*D_MODEL];
__device__ __half g_k   [TOKI*D_MODEL];
__device__ __half g_v   [TOKI*D_MODEL];
__device__ __half g_attn[TOKP*D_MODEL];
__device__ __half g_h   [TOKP*D_MODEL];
__device__ __half g_wh  [10][WELEM];   /* fp16 weights, [k][n] layout */

// ---------------- helpers ----------------
__device__ __forceinline__ void cpa16(uint32_t sa, const void* g) {
    asm volatile("cp.async.cg.shared.global [%0], [%1], 16;" :: "r"(sa), "l"(g));
}
__device__ __forceinline__ void cp_commit() { asm volatile("cp.async.commit_group;"); }
__device__ __forceinline__ uint32_t su32(const void* p) {
    return (uint32_t)__cvta_generic_to_shared(p);
}

// ---------------- fused weight fp32 -> fp16 (all 10 matrices, one launch) ----------------
struct WSrc { const float* p[10]; };
__global__ void half_w_all_kernel(WSrc S, __half* __restrict__ dst) {
    int mat = blockIdx.y;
    int i = blockIdx.x * blockDim.x + threadIdx.x;
    const float4* s = (const float4*)S.p[mat];
    float4 v = s[i];
    __half* d = dst + (size_t)mat * WELEM + (size_t)i * 4;
    *(__half2*)&d[0] = __floats2half2_rn(v.x, v.y);
    *(__half2*)&d[2] = __floats2half2_rn(v.z, v.w);
}

// ---------------- elementwise add (float4) ----------------
__global__ void add4_kernel(const float4* __restrict__ a, const float4* __restrict__ b,
                            float4* __restrict__ o, int n4) {
    int i = blockIdx.x * blockDim.x + threadIdx.x;
    if (i < n4) {
        float4 x = a[i], y = b[i];
        x.x += y.x; x.y += y.y; x.z += y.z; x.w += y.w;
        o[i] = x;
    }
}

// ---------------- (optional add) + layernorm -> fp16 ----------------
__global__ void addln_kernel(const float* __restrict__ a, const float* __restrict__ b,
                             const float* __restrict__ g, const float* __restrict__ be,
                             __half* __restrict__ o) {
    int row = blockIdx.x;
    const float* pa = a + (size_t)row * D_MODEL;
    const float* pb = b ? b + (size_t)row * D_MODEL : nullptr;
    float x[3];
    float s = 0.f, sq = 0.f;
#pragma unroll
    for (int j = 0; j < 3; j++) {
        int i = threadIdx.x + j * 256;
        float v = pa[i];
        if (pb) v += pb[i];
        x[j] = v; s += v; sq += v * v;
    }
    __shared__ float sb[16];
    unsigned wid = threadIdx.x >> 5, lane = threadIdx.x & 31;
#pragma unroll
    for (int off = 16; off; off >>= 1) {
        s  += __shfl_xor_sync(0xffffffffu, s,  off);
        sq += __shfl_xor_sync(0xffffffffu, sq, off);
    }
    if (lane == 0) { sb[wid] = s; sb[8 + wid] = sq; }
    __syncthreads();
    if (threadIdx.x < 32) {
        float s2 = (lane < 8) ? sb[lane] : 0.f;
        float q2 = (lane < 8) ? sb[8 + lane] : 0.f;
#pragma unroll
        for (int off = 4; off; off >>= 1) {
            s2 += __shfl_xor_sync(0xffffffffu, s2, off);
            q2 += __shfl_xor_sync(0xffffffffu, q2, off);
        }
        if (lane == 0) { sb[0] = s2; sb[1] = q2; }
    }
    __syncthreads();
    float mean = sb[0] * (1.f / 768.f);
    float var  = sb[1] * (1.f / 768.f) - mean * mean;
    float rs   = rsqrtf(var + 1e-5f);
#pragma unroll
    for (int j = 0; j < 3; j++) {
        int i = threadIdx.x + j * 256;
        o[(size_t)row * D_MODEL + i] = __float2half_rn((x[j] - mean) * rs * g[i] + be[i]);
    }
}

// ---------------- wmma fp16 typedefs ----------------
using HFragA  = wmma::fragment<wmma::matrix_a, 16, 16, 16, __half, wmma::row_major>;
using HFragB  = wmma::fragment<wmma::matrix_b, 16, 16, 16, __half, wmma::row_major>;
using HFragBT = wmma::fragment<wmma::matrix_b, 16, 16, 16, __half, wmma::col_major>;
using HFragC  = wmma::fragment<wmma::accumulator, 16, 16, 16, float>;

extern __shared__ __align__(16) char smraw[];

// ===== dense GEMM: 128x128xK64 fp16, warp 64x32, cp.async 3-stage, 1 sync/iter =====
struct DZ {
    const __half* W[3];
    const float*  Bi[3];
    const float*  R[3];
    float*  Cf[3];
    __half* Ch[3];
    int fl[3];
};

#define D_ALD 72
#define D_BLD 136
#define D_ASZ (128 * D_ALD)
#define D_BSZ (64 * D_BLD)
#define D_STG (D_ASZ + D_BSZ)        /* 17920 halves = 35840 B */
#define D_CLD 132
#define DENSE_SMEM (3 * D_STG * 2)   /* 107520 B; 2 CTAs = 215KB fits */

__global__ __launch_bounds__(256, 2) void dense_gemm_kernel(
    const __half* __restrict__ A, DZ P, int M) {
    constexpr int K = D_MODEL, N = D_MODEL;
    const __half* W    = P.W[blockIdx.z];
    const float* bias  = P.Bi[blockIdx.z];
    const float* resid = P.R[blockIdx.z];
    float*  Cf         = P.Cf[blockIdx.z];
    __half* Ch         = P.Ch[blockIdx.z];
    int flags          = P.fl[blockIdx.z];

    __half* sm = (__half*)smraw;
    int tid = threadIdx.x;
    int m0 = blockIdx.y * 128, n0 = blockIdx.x * 128;
    int warp = tid >> 5, wm = warp & 1, wn = warp >> 1;

    HFragC acc[4][2];
#pragma unroll
    for (int i = 0; i < 4; i++)
#pragma unroll
        for (int j = 0; j < 2; j++) wmma::fill_fragment(acc[i][j], 0.f);

    auto load_tile = [&](int s, int k0) {
        __half* As = sm + s * D_STG;
        __half* Bs = As + D_ASZ;
#pragma unroll
        for (int i = 0; i < 4; i++) {
            int p = tid + i * 256, r = p >> 3, c = (p & 7) * 8;
            cpa16(su32(&As[r * D_ALD + c]), &A[(size_t)(m0 + r) * K + k0 + c]);
        }
#pragma unroll
        for (int i = 0; i < 4; i++) {
            int p = tid + i * 256, r = p >> 4, c = (p & 15) * 8;
            cpa16(su32(&Bs[r * D_BLD + c]), &W[(size_t)(k0 + r) * N + n0 + c]);
        }
        cp_commit();
    };

    const int nk = K / 64;   // 12
    load_tile(0, 0);
    load_tile(1, 64);
    for (int kt = 0; kt < nk; kt++) {
        int s = kt % 3;
        if (kt + 1 < nk) asm volatile("cp.async.wait_group 1;");
        else             asm volatile("cp.async.wait_group 0;");
        __syncthreads();
        if (kt + 2 < nk) load_tile((kt + 2) % 3, (kt + 2) * 64);
        __half* As = sm + s * D_STG;
        __half* Bs = As + D_ASZ;
#pragma unroll
        for (int kk = 0; kk < 64; kk += 16) {
            HFragA fa[4]; HFragB fb[2];
#pragma unroll
            for (int i = 0; i < 4; i++)
                wmma::load_matrix_sync(fa[i], &As[(wm * 64 + i * 16) * D_ALD + kk], D_ALD);
#pragma unroll
            for (int j = 0; j < 2; j++)
                wmma::load_matrix_sync(fb[j], &Bs[kk * D_BLD + wn * 32 + j * 16], D_BLD);
#pragma unroll
            for (int i = 0; i < 4; i++)
#pragma unroll
                for (int j = 0; j < 2; j++) wmma::mma_sync(acc[i][j], fa[i], fb[j], acc[i][j]);
        }
    }
    __syncthreads();
    float* Cs = (float*)smraw;
#pragma unroll
    for (int i = 0; i < 4; i++)
#pragma unroll
        for (int j = 0; j < 2; j++)
            wmma::store_matrix_sync(&Cs[(wm * 64 + i * 16) * D_CLD + wn * 32 + j * 16],
                                    acc[i][j], D_CLD, wmma::mem_row_major);
    __syncthreads();
#pragma unroll
    for (int i = 0; i < 16; i++) {
        int p = tid + i * 256, r = p >> 5, c = (p & 31) * 4;
        float4 v = *(float4*)&Cs[r * D_CLD + c];
        int gc = n0 + c;
        float4 bv = *(const float4*)&bias[gc];
        v.x += bv.x; v.y += bv.y; v.z += bv.z; v.w += bv.w;
        size_t off = (size_t)(m0 + r) * N + gc;
        if (resid) {
            float4 rv = *(const float4*)&resid[off];
            v.x += rv.x; v.y += rv.y; v.z += rv.z; v.w += rv.w;
        }
        if (flags & 1) {
            v.x = fmaxf(v.x, 0.f); v.y = fmaxf(v.y, 0.f);
            v.z = fmaxf(v.z, 0.f); v.w = fmaxf(v.w, 0.f);
        }
        if (flags & 2) {
            *(__half2*)&Ch[off]     = __floats2half2_rn(v.x, v.y);
            *(__half2*)&Ch[off + 2] = __floats2half2_rn(v.z, v.w);
        } else {
            *(float4*)&Cf[off] = v;
        }
    }
}

// ===== fused attention: 128 q-rows x one head per CTA; two-pass softmax, 2 CTAs/SM =====
#define FA_QS 0                      /* 128 x 72 halves = 18432 */
#define FA_KS 18432                  /* 2 x (64 x 72 halves)    = 18432 */
#define FA_VS 36864                  /* 2 x (64 x 72 halves)    = 18432 */
#define FA_SS 55296                  /* 128 x 68 fp32           = 34816 */
#define FA_PS 90112                  /* 128 x 72 halves         = 18432 */
#define FA_MS 108544                 /* 128 fp32 = 512 */
#define FA_LS 109056                 /* 128 fp32 = 512 */
#define FA_SMEM 109568               /* x2 CTAs = 219KB fits */

__global__ __launch_bounds__(256, 2) void fattn_kernel(
    const __half* __restrict__ Q, const __half* __restrict__ Kg,
    const __half* __restrict__ Vg, __half* __restrict__ O, int kv_tokens) {
    const float alpha = 0.125f;
    int z = blockIdx.y, bi = z / HEADS, hi = z % HEADS;
    int m0 = blockIdx.x * 128;
    const __half* Qb = Q  + ((size_t)bi * SP + m0) * D_MODEL + hi * D_HEAD;
    const __half* Kb = Kg + (size_t)bi * kv_tokens * D_MODEL + hi * D_HEAD;
    const __half* Vb = Vg + (size_t)bi * kv_tokens * D_MODEL + hi * D_HEAD;
    __half* Ob = O + ((size_t)bi * SP + m0) * D_MODEL + hi * D_HEAD;

    __half* Qs = (__half*)(smraw + FA_QS);
    __half* Ks = (__half*)(smraw + FA_KS);
    __half* Vs = (__half*)(smraw + FA_VS);
    float*  Ss = (float*)(smraw + FA_SS);
    __half* Ps = (__half*)(smraw + FA_PS);
    float*  Ms = (float*)(smraw + FA_MS);
    float*  Ls = (float*)(smraw + FA_LS);

    int tid = threadIdx.x;
    int warp = tid >> 5, wm = warp & 3, wn = warp >> 2;

#pragma unroll
    for (int i = 0; i < 4; i++) {
        int p = tid + i * 256, r = p >> 3, c = (p & 7) * 8;
        cpa16(su32(&Qs[r * 72 + c]), &Qb[(size_t)r * D_MODEL + c]);
    }
    cp_commit();
    if (tid < 128) { Ms[tid] = -1e30f; Ls[tid] = 0.f; }
    asm volatile("cp.async.wait_group 0;");
    __syncthreads();

    const int nt = kv_tokens / 64;

    auto load_k = [&](int t, int s) {
#pragma unroll
        for (int i = 0; i < 2; i++) {
            int p = tid + i * 256, r = p >> 3, c = (p & 7) * 8;
            cpa16(su32(&Ks[s * 4608 + r * 72 + c]), &Kb[(size_t)(t * 64 + r) * D_MODEL + c]);
        }
    };
    auto load_v = [&](int t, int s) {
#pragma unroll
        for (int i = 0; i < 2; i++) {
            int p = tid + i * 256, r = p >> 3, c = (p & 7) * 8;
            cpa16(su32(&Vs[s * 4608 + r * 72 + c]), &Vb[(size_t)(t * 64 + r) * D_MODEL + c]);
        }
    };
    auto s_mma_store = [&](int s) {
        HFragC sacc[2][2];
#pragma unroll
        for (int i = 0; i < 2; i++)
#pragma unroll
            for (int j = 0; j < 2; j++) wmma::fill_fragment(sacc[i][j], 0.f);
#pragma unroll
        for (int kk = 0; kk < 64; kk += 16) {
            HFragA fa[2]; HFragBT fb[2];
#pragma unroll
            for (int i = 0; i < 2; i++)
                wmma::load_matrix_sync(fa[i], &Qs[(wm * 32 + i * 16) * 72 + kk], 72);
#pragma unroll
            for (int j = 0; j < 2; j++)
                wmma::load_matrix_sync(fb[j], &Ks[s * 4608 + (wn * 32 + j * 16) * 72 + kk], 72);
#pragma unroll
            for (int i = 0; i < 2; i++)
#pragma unroll
                for (int j = 0; j < 2; j++) wmma::mma_sync(sacc[i][j], fa[i], fb[j], sacc[i][j]);
        }
#pragma unroll
        for (int i = 0; i < 2; i++)
#pragma unroll
            for (int j = 0; j < 2; j++)
                wmma::store_matrix_sync(&Ss[(wm * 32 + i * 16) * 68 + wn * 32 + j * 16],
                                        sacc[i][j], 68, wmma::mem_row_major);
    };

    // ---------- PASS 1: row stats (2 threads/row, shfl-combined, fast exp) ----------
    load_k(0, 0); cp_commit();
    for (int t = 0; t < nt; t++) {
        int s = t & 1;
        asm volatile("cp.async.wait_group 0;");
        __syncthreads();
        s_mma_store(s);
        if (t + 1 < nt) { load_k(t + 1, s ^ 1); cp_commit(); }
        __syncthreads();
        {
            int r = tid >> 1, hf = tid & 1;
            const float* Sr = Ss + r * 68 + hf * 32;
            float m_old = Ms[r], l_old = Ls[r];
            float tm = -1e30f;
#pragma unroll
            for (int j = 0; j < 32; j++) tm = fmaxf(tm, Sr[j]);
            tm *= alpha;
            float tmo = __shfl_xor_sync(0xffffffffu, tm, 1);
            float m_new = fmaxf(fmaxf(tm, tmo), m_old);
            float sum = 0.f;
#pragma unroll
            for (int j = 0; j < 32; j++) sum += __expf(Sr[j] * alpha - m_new);
            sum += __shfl_xor_sync(0xffffffffu, sum, 1);
            if (hf == 0) {
                Ls[r] = l_old * __expf(m_old - m_new) + sum;
                Ms[r] = m_new;
            }
        }
        __syncthreads();
    }
    if (tid < 128) Ls[tid] = 1.f / Ls[tid];
    __syncthreads();

    // ---------- PASS 2: P = exp(s-m)/l ; O += P@V ----------
    HFragC oacc[2][2];
#pragma unroll
    for (int i = 0; i < 2; i++)
#pragma unroll
        for (int j = 0; j < 2; j++) wmma::fill_fragment(oacc[i][j], 0.f);

    load_k(0, 0); load_v(0, 0); cp_commit();
    for (int t = 0; t < nt; t++) {
        int s = t & 1;
        asm volatile("cp.async.wait_group 0;");
        __syncthreads();
        s_mma_store(s);
        if (t + 1 < nt) { load_k(t + 1, s ^ 1); load_v(t + 1, s ^ 1); cp_commit(); }
        __syncthreads();
        {
            int r = tid >> 1, cb = (tid & 1) * 32;
            float m = Ms[r], li = Ls[r];
            const float* Sr = Ss + r * 68 + cb;
            __half* Pr = Ps + r * 72 + cb;
#pragma unroll
            for (int j = 0; j < 32; j += 2) {
                float a = __expf(Sr[j] * alpha - m) * li;
                float b = __expf(Sr[j + 1] * alpha - m) * li;
                *(__half2*)&Pr[j] = __floats2half2_rn(a, b);
            }
        }
        __syncthreads();
#pragma unroll
        for (int kk = 0; kk < 64; kk += 16) {
            HFragA fa[2]; HFragB fb[2];
#pragma unroll
            for (int i = 0; i < 2; i++)
                wmma::load_matrix_sync(fa[i], &Ps[(wm * 32 + i * 16) * 72 + kk], 72);
#pragma unroll
            for (int j = 0; j < 2; j++)
                wmma::load_matrix_sync(fb[j], &Vs[s * 4608 + kk * 72 + wn * 32 + j * 16], 72);
#pragma unroll
            for (int i = 0; i < 2; i++)
#pragma unroll
                for (int j = 0; j < 2; j++) wmma::mma_sync(oacc[i][j], fa[i], fb[j], oacc[i][j]);
        }
        __syncthreads();
    }
#pragma unroll
    for (int i = 0; i < 2; i++)
#pragma unroll
        for (int j = 0; j < 2; j++)
            wmma::store_matrix_sync(&Ss[(wm * 32 + i * 16) * 68 + wn * 32 + j * 16],
                                    oacc[i][j], 68, wmma::mem_row_major);
    __syncthreads();
#pragma unroll
    for (int i = 0; i < 16; i++) {
        int p = tid + i * 256;          // 4096 half2 units = 128x64
        int r = p >> 5, c2 = (p & 31) * 2;
        float a = Ss[r * 68 + c2], b = Ss[r * 68 + c2 + 1];
        *(__half2*)&Ob[(size_t)r * D_MODEL + c2] = __floats2half2_rn(a, b);
    }
}

// ---------------- launcher ----------------
extern "C" void kernel_launch(void* const* d_in, const int* in_sizes, int n_in,
                              void* d_out, int out_size) {
    (void)in_sizes; (void)n_in; (void)out_size;
    const float* image  = (const float*)d_in[0];
    const float* prompt = (const float*)d_in[1];
    const float* posi   = (const float*)d_in[2];
    const float* posp   = (const float*)d_in[3];
    const float* ln1g = (const float*)d_in[4],  *ln1b = (const float*)d_in[5];
    const float* ln2g = (const float*)d_in[6],  *ln2b = (const float*)d_in[7];
    const float* ln3g = (const float*)d_in[8],  *ln3b = (const float*)d_in[9];
    const float* lnig = (const float*)d_in[10], *lnib = (const float*)d_in[11];
    const float* pp_wq = (const float*)d_in[12], *pp_bq = (const float*)d_in[13];
    const float* pp_wk = (const float*)d_in[14], *pp_bk = (const float*)d_in[15];
    const float* pp_wv = (const float*)d_in[16], *pp_bv = (const float*)d_in[17];
    const float* pp_wo = (const float*)d_in[18], *pp_bo = (const float*)d_in[19];
    const float* pi_wq = (const float*)d_in[20], *pi_bq = (const float*)d_in[21];
    const float* pi_wk = (const float*)d_in[22], *pi_bk = (const float*)d_in[23];
    const float* pi_wv = (const float*)d_in[24], *pi_bv = (const float*)d_in[25];
    const float* pi_wo = (const float*)d_in[26], *pi_bo = (const float*)d_in[27];
    const float* ff_w1 = (const float*)d_in[28], *ff_b1 = (const float*)d_in[29];
    const float* ff_w2 = (const float*)d_in[30], *ff_b2 = (const float*)d_in[31];
    float* out = (float*)d_out;

    float *prompt0, *p1, *p2;
    __half *x, *xi, *q, *k, *v, *attn, *h, *wh;
    cudaGetSymbolAddress((void**)&prompt0, g_prompt0);
    cudaGetSymbolAddress((void**)&p1,    g_p1);
    cudaGetSymbolAddress((void**)&p2,    g_p2);
    cudaGetSymbolAddress((void**)&x,     g_x);
    cudaGetSymbolAddress((void**)&xi,    g_xi);
    cudaGetSymbolAddress((void**)&q,     g_q);
    cudaGetSymbolAddress((void**)&k,     g_k);
    cudaGetSymbolAddress((void**)&v,     g_v);
    cudaGetSymbolAddress((void**)&attn,  g_attn);
    cudaGetSymbolAddress((void**)&h,     g_h);
    cudaGetSymbolAddress((void**)&wh,    g_wh);

    __half* W[10];
    const float* srcw[10] = {pp_wq, pp_wk, pp_wv, pp_wo, pi_wq, pi_wk, pi_wv, pi_wo, ff_w1, ff_w2};
    for (int i = 0; i < 10; i++) W[i] = wh + (size_t)i * WELEM;

    cudaFuncSetAttribute(dense_gemm_kernel, cudaFuncAttributeMaxDynamicSharedMemorySize, DENSE_SMEM);
    cudaFuncSetAttribute(fattn_kernel,      cudaFuncAttributeMaxDynamicSharedMemorySize, FA_SMEM);

    // 0. all weights -> fp16, one launch
    {
        WSrc S; for (int i = 0; i < 10; i++) S.p[i] = srcw[i];
        half_w_all_kernel<<<dim3(WELEM / 4 / 256, 10), 256>>>(S, wh);
    }
    // 1. prompt0 = prompt + posp
    add4_kernel<<<(TOKP * D_MODEL / 4 + 255) / 256, 256>>>(
        (const float4*)prompt, (const float4*)posp, (float4*)prompt0, TOKP * D_MODEL / 4);
    // 2. x = LN(prompt0) -> fp16
    addln_kernel<<<TOKP, 256>>>(prompt0, nullptr, ln1g, ln1b, x);
    // 3. self QKV fused (z=3) -> fp16
    {
        DZ P = {{W[0], W[1], W[2]}, {pp_bq, pp_bk, pp_bv}, {nullptr, nullptr, nullptr},
                {nullptr, nullptr, nullptr}, {q, k, v}, {2, 2, 2}};
        dense_gemm_kernel<<<dim3(6, 32, 3), 256, DENSE_SMEM>>>(x, P, TOKP);
    }
    // 4. fused self-attention -> attn (fp16)
    fattn_kernel<<<dim3(SP / 128, NB * HEADS), 256, FA_SMEM>>>(q, k, v, attn, SP);
    // 5. p1 = attn @ Wo + bo + prompt (fp32)
    {
        DZ P = {{W[3], nullptr, nullptr}, {pp_bo, nullptr, nullptr}, {prompt, nullptr, nullptr},
                {p1, nullptr, nullptr}, {nullptr, nullptr, nullptr}, {0, 0, 0}};
        dense_gemm_kernel<<<dim3(6, 32, 1), 256, DENSE_SMEM>>>(attn, P, TOKP);
    }
    // 6. x = LN(p1 + prompt0) -> fp16
    addln_kernel<<<TOKP, 256>>>(p1, prompt0, ln2g, ln2b, x);
    // 7. xi = LN(image + posi) -> fp16
    addln_kernel<<<TOKI, 256>>>(image, posi, lnig, lnib, xi);
    // 8. cross Q -> fp16
    {
        DZ P = {{W[4], nullptr, nullptr}, {pi_bq, nullptr, nullptr}, {nullptr, nullptr, nullptr},
                {nullptr, nullptr, nullptr}, {q, nullptr, nullptr}, {2, 0, 0}};
        dense_gemm_kernel<<<dim3(6, 32, 1), 256, DENSE_SMEM>>>(x, P, TOKP);
    }
    // 9. image K,V fused (z=2) -> fp16
    {
        DZ P = {{W[5], W[6], nullptr}, {pi_bk, pi_bv, nullptr}, {nullptr, nullptr, nullptr},
                {nullptr, nullptr, nullptr}, {k, v, nullptr}, {2, 2, 0}};
        dense_gemm_kernel<<<dim3(6, 128, 2), 256, DENSE_SMEM>>>(xi, P, TOKI);
    }
    // 10. fused cross-attention -> attn (fp16)
    fattn_kernel<<<dim3(SP / 128, NB * HEADS), 256, FA_SMEM>>>(q, k, v, attn, SI);
    // 11. p2 = attn @ Wo + bo + p1 (fp32)
    {
        DZ P = {{W[7], nullptr, nullptr}, {pi_bo, nullptr, nullptr}, {p1, nullptr, nullptr},
                {p2, nullptr, nullptr}, {nullptr, nullptr, nullptr}, {0, 0, 0}};
        dense_gemm_kernel<<<dim3(6, 32, 1), 256, DENSE_SMEM>>>(attn, P, TOKP);
    }
    // 12. x = LN(p2 + prompt0) -> fp16
    addln_kernel<<<TOKP, 256>>>(p2, prompt0, ln3g, ln3b, x);
    // 13. h = relu(x @ W1 + b1) -> fp16
    {
        DZ P = {{W[8], nullptr, nullptr}, {ff_b1, nullptr, nullptr}, {nullptr, nullptr, nullptr},
                {nullptr, nullptr, nullptr}, {h, nullptr, nullptr}, {3, 0, 0}};
        dense_gemm_kernel<<<dim3(6, 32, 1), 256, DENSE_SMEM>>>(x, P, TOKP);
    }
    // 14. out = h @ W2 + b2 (fp32 final)
    {
        DZ P = {{W[9], nullptr, nullptr}, {ff_b2, nullptr, nullptr}, {nullptr, nullptr, nullptr},
                {out, nullptr, nullptr}, {nullptr, nullptr, nullptr}, {0, 0, 0}};
        dense_gemm_kernel<<<dim3(6, 32, 1), 256, DENSE_SMEM>>>(h, P, TOKP);
    }
}